// round 6
// baseline (speedup 1.0000x reference)
#include <cuda_runtime.h>
#include <cuda_fp16.h>
#include <math.h>

#define NN   50000
#define E1   300000
#define EN   30000
#define ET   330000
#define OREL 12800000      // 50000*256
#define O3   12865536      // + 256*256
#define NREL 256

// ---------------- device scratch (static, allocation-free) ----------------
#define OFF_S1   0                       // [NN*256]
#define OFF_S2   (NN*256)                // [NN*256]
#define OFF_RS1  (2*NN*256)              // [2*NN]
#define OFF_RS2  (2*NN*256 + 2*NN)       // [NN]
#define OFF_MASK (2*NN*256 + 3*NN)       // [NN]
#define ZN       (2*NN*256 + 4*NN)
__device__ float g_Z[ZN];

__device__ __half g_entH[NN*128];
__device__ __half g_xH  [NN*256];
__device__ __half g_orelH[256*256];
__device__ __half g_PsH [NN*256];
__device__ __half g_XsH [NN*256];
__device__ __half g_R1H [NREL*256];
__device__ __half g_R2H [NREL*256];
__device__ float  g_eup [NN*256];
__device__ float  g_Xd  [NN*256];
__device__ float  g_sd1[2*NN];
__device__ float  g_ss1[2*NN];
__device__ float  g_sr1[2*NREL];
__device__ float  g_sd2[NN];
__device__ float  g_ss2[NN];
__device__ float  g_sr2[NREL];
__device__ float  g_wv [1536];   // w_d(256)|w_s(256)|w_r(256)|w2d(256)|w2s(256)|w2r(256)
// packed fp16 B matrices ([N][K] row-major for TN gemm) + relH
__device__ __half hB1d[512*128];
__device__ __half hB1s[256*128];
__device__ __half hBR1[256*128];
__device__ __half hB2d[256*256];
__device__ __half hB2s[256*256];
__device__ __half hB3 [256*256];
__device__ __half hBW [256*128];
__device__ __half g_relH[256*128];

// ---------------- helpers ----------------
__device__ __forceinline__ float4 ld4(const float* p){ return *reinterpret_cast<const float4*>(p); }
__device__ __forceinline__ void   st4(float* p, float4 v){ *reinterpret_cast<float4*>(p) = v; }
__device__ __forceinline__ float  elu1(float x){ return x > 0.f ? x : expm1f(x); }
__device__ __forceinline__ float  wred(float v){
    #pragma unroll
    for (int o = 16; o; o >>= 1) v += __shfl_xor_sync(0xffffffffu, v, o);
    return v;
}
__device__ __forceinline__ void red4(float* p, float4 v){
    asm volatile("red.global.add.v4.f32 [%0], {%1, %2, %3, %4};"
                 :: "l"(p), "f"(v.x), "f"(v.y), "f"(v.z), "f"(v.w) : "memory");
}
__device__ __forceinline__ float dot4(float4 a, float4 b){
    return a.x*b.x + a.y*b.y + a.z*b.z + a.w*b.w;
}
__device__ __forceinline__ void mma_f16(float* c, const unsigned* a, const unsigned* b){
    asm volatile("mma.sync.aligned.m16n8k16.row.col.f32.f16.f16.f32 "
        "{%0,%1,%2,%3}, {%4,%5,%6,%7}, {%8,%9}, {%0,%1,%2,%3};"
        : "+f"(c[0]), "+f"(c[1]), "+f"(c[2]), "+f"(c[3])
        : "r"(a[0]), "r"(a[1]), "r"(a[2]), "r"(a[3]), "r"(b[0]), "r"(b[1]));
}
__device__ __forceinline__ void ldm4(unsigned& r0, unsigned& r1, unsigned& r2, unsigned& r3, unsigned a){
    asm volatile("ldmatrix.sync.aligned.m8n8.x4.shared.b16 {%0,%1,%2,%3}, [%4];"
        : "=r"(r0), "=r"(r1), "=r"(r2), "=r"(r3) : "r"(a));
}
__device__ __forceinline__ void cpasync16(unsigned dst, const void* src, int sz){
    asm volatile("cp.async.cg.shared.global [%0], [%1], 16, %2;"
                 :: "r"(dst), "l"(src), "r"(sz) : "memory");
}
__device__ __forceinline__ void cp_commit(){ asm volatile("cp.async.commit_group;" ::: "memory"); }
__device__ __forceinline__ void cp_wait1(){ asm volatile("cp.async.wait_group 1;" ::: "memory"); }

// ---------------- zero fill ----------------
__global__ void k_zero4(float4* __restrict__ p, int n4){
    int i  = blockIdx.x * blockDim.x + threadIdx.x;
    int st = gridDim.x * blockDim.x;
    float4 z = make_float4(0,0,0,0);
    for (; i < n4; i += st) p[i] = z;
}

// ---------------- pack all fp16 B matrices + relH ----------------
__global__ void k_packs(const float* __restrict__ a1, const float* __restrict__ a_out,
                        const float* __restrict__ W,  const float* __restrict__ W_ent,
                        const float* __restrict__ rel,
                        __half* __restrict__ B1d, __half* __restrict__ B1s,
                        __half* __restrict__ BR1, __half* __restrict__ B2d,
                        __half* __restrict__ B2s, __half* __restrict__ B3,
                        __half* __restrict__ BW,  __half* __restrict__ relH)
{
    int i = blockIdx.x * blockDim.x + threadIdx.x;
    if (i < 512*128){
        int r = i >> 7, k = i & 127;
        float v;
        if (r < 256){ int h = r >> 7, rr = r & 127; v = a1[h*128*384 + rr*384 + k]; }
        else        { v = W_ent[k*256 + (r - 256)]; }
        B1d[i] = __float2half_rn(v); return;
    }
    i -= 512*128;
    if (i < 256*128){
        int r = i >> 7, k = i & 127; int h = r >> 7, rr = r & 127;
        B1s[i] = __float2half_rn(a1[h*128*384 + rr*384 + 128 + k]); return;
    }
    i -= 256*128;
    if (i < 256*128){
        int r = i >> 7, k = i & 127; int h = r >> 7, rr = r & 127;
        BR1[i] = __float2half_rn(a1[h*128*384 + rr*384 + 256 + k]); return;
    }
    i -= 256*128;
    if (i < 256*256){ int r = i >> 8, k = i & 255; B2d[i] = __float2half_rn(a_out[r*768 + k]);       return; }
    i -= 256*256;
    if (i < 256*256){ int r = i >> 8, k = i & 255; B2s[i] = __float2half_rn(a_out[r*768 + 256 + k]); return; }
    i -= 256*256;
    if (i < 256*256){ int r = i >> 8, k = i & 255; B3[i]  = __float2half_rn(a_out[r*768 + 512 + k]); return; }
    i -= 256*256;
    if (i < 256*128){ int r = i >> 7, k = i & 127; BW[i]  = __float2half_rn(W[k*256 + r]);           return; }
    i -= 256*128;
    if (i < 256*128){ relH[i] = __float2half_rn(rel[i]); return; }
}

// ---------------- row l2-normalize, D=128, warp/row, fp16 out ----------------
__global__ void k_l2norm128(const float* __restrict__ in, __half* __restrict__ out){
    int n = (blockIdx.x * blockDim.x + threadIdx.x) >> 5;
    int lane = threadIdx.x & 31;
    if (n >= NN) return;
    int c = lane * 4;
    float4 v = ld4(in + (size_t)n*128 + c);
    float ss = dot4(v, v);
    ss = wred(ss);
    float s = 1.f / fmaxf(sqrtf(ss), 1e-12f);
    *reinterpret_cast<__half2*>(out + (size_t)n*128 + c)     = __floats2half2_rn(v.x*s, v.y*s);
    *reinterpret_cast<__half2*>(out + (size_t)n*128 + c + 2) = __floats2half2_rn(v.z*s, v.w*s);
}

// ---------------- mask ----------------
__global__ void k_setmask(const int* __restrict__ bi, float* __restrict__ mask){
    int i = blockIdx.x * blockDim.x + threadIdx.x;
    if (i < 4096) mask[bi[3*i + 2]] = 1.f;
}

// ---------------- w vectors: w = B^T a2 (nine tiny column dots) ----------------
__global__ void k_wvec(const __half* __restrict__ B1d, const __half* __restrict__ B1s,
                       const __half* __restrict__ BR1, const __half* __restrict__ B2d,
                       const __half* __restrict__ B2s, const __half* __restrict__ B3,
                       const float* __restrict__ a2_1, const float* __restrict__ a2_out,
                       float* __restrict__ wv)
{
    int b = blockIdx.x, k = threadIdx.x;
    if (b < 6){
        if (k >= 128) return;
        const __half* B = (b < 2) ? B1d : (b < 4) ? B1s : BR1;
        int h = b & 1;
        const __half* Bh = B + (size_t)h*128*128;
        const float* a2 = a2_1 + h*128;
        float acc = 0.f;
        for (int j = 0; j < 128; j++)
            acc += __half2float(Bh[j*128 + k]) * a2[j];
        wv[(b >> 1)*256 + h*128 + k] = acc;
    } else {
        const __half* B = (b == 6) ? B2d : (b == 7) ? B2s : B3;
        float acc = 0.f;
        for (int j = 0; j < 256; j++)
            acc += __half2float(B[j*256 + k]) * a2_out[j];
        wv[768 + (b - 6)*256 + k] = acc;
    }
}

// ---------------- layer-1 node attention scalars from entH ----------------
__global__ void k_scal1(const __half* __restrict__ entH, const float* __restrict__ wv,
                        float* __restrict__ sd, float* __restrict__ ss){
    int n = (blockIdx.x * blockDim.x + threadIdx.x) >> 5;
    int lane = threadIdx.x & 31;
    if (n >= NN) return;
    int c = lane * 4;
    const __half2* ep = reinterpret_cast<const __half2*>(entH + (size_t)n*128 + c);
    float2 e0 = __half22float2(ep[0]), e1 = __half22float2(ep[1]);
    float4 e = make_float4(e0.x, e0.y, e1.x, e1.y);
    float d0 = dot4(e, ld4(wv + c));
    float d1 = dot4(e, ld4(wv + 128 + c));
    float s0 = dot4(e, ld4(wv + 256 + c));
    float s1 = dot4(e, ld4(wv + 384 + c));
    d0 = wred(d0); d1 = wred(d1); s0 = wred(s0); s1 = wred(s1);
    if (lane == 0){ sd[n] = d0; sd[NN + n] = d1; ss[n] = s0; ss[NN + n] = s1; }
}

// ---------------- layer-1 relation scalars from relH ----------------
__global__ void k_scalrel1(const __half* __restrict__ relH, const float* __restrict__ wv,
                           float* __restrict__ sr){
    int r = (blockIdx.x * blockDim.x + threadIdx.x) >> 5;
    int lane = threadIdx.x & 31;
    if (r >= NREL) return;
    int c = lane * 4;
    const __half2* ep = reinterpret_cast<const __half2*>(relH + (size_t)r*128 + c);
    float2 e0 = __half22float2(ep[0]), e1 = __half22float2(ep[1]);
    float4 e = make_float4(e0.x, e0.y, e1.x, e1.y);
    float v0 = dot4(e, ld4(wv + 512 + c));
    float v1 = dot4(e, ld4(wv + 640 + c));
    v0 = wred(v0); v1 = wred(v1);
    if (lane == 0){ sr[r] = v0; sr[NREL + r] = v1; }
}

// ---------------- layer-2 node scalars from xH ----------------
__global__ void k_scal2(const __half* __restrict__ xH, const float* __restrict__ wv,
                        float* __restrict__ sd, float* __restrict__ ss){
    int n = (blockIdx.x * blockDim.x + threadIdx.x) >> 5;
    int lane = threadIdx.x & 31;
    if (n >= NN) return;
    float d = 0.f, s = 0.f;
    #pragma unroll
    for (int c0 = 0; c0 < 256; c0 += 128){
        int c = c0 + lane*4;
        const __half2* ep = reinterpret_cast<const __half2*>(xH + (size_t)n*256 + c);
        float2 e0 = __half22float2(ep[0]), e1 = __half22float2(ep[1]);
        float4 e = make_float4(e0.x, e0.y, e1.x, e1.y);
        d += dot4(e, ld4(wv + 768 + c));
        s += dot4(e, ld4(wv + 1024 + c));
    }
    d = wred(d); s = wred(s);
    if (lane == 0){ sd[n] = d; ss[n] = s; }
}

// ---------------- layer-2 relation scalars from orelH ----------------
__global__ void k_scalrel2(const __half* __restrict__ orelH, const float* __restrict__ wv,
                           float* __restrict__ sr){
    int r = (blockIdx.x * blockDim.x + threadIdx.x) >> 5;
    int lane = threadIdx.x & 31;
    if (r >= NREL) return;
    float v = 0.f;
    #pragma unroll
    for (int c0 = 0; c0 < 256; c0 += 128){
        int c = c0 + lane*4;
        const __half2* ep = reinterpret_cast<const __half2*>(orelH + (size_t)r*256 + c);
        float2 e0 = __half22float2(ep[0]), e1 = __half22float2(ep[1]);
        float4 e = make_float4(e0.x, e0.y, e1.x, e1.y);
        v += dot4(e, ld4(wv + 1280 + c));
    }
    v = wred(v);
    if (lane == 0) sr[r] = v;
}

// ---------------- FP16 tensor-core GEMM (TN), ldmatrix + cp.async double-buffer ----
// EPI: 0 = fp32 C; 1 = fp32 C + fp16 Ch; 2 = fp16 Ch only; 3 = fused fin1/eup
// (EPI 3: N=512; cols<256 -> xH = elu((rs*acc+S)/rs), cols>=256 -> eup fp32)
#define SA 40
#define MATB (128*SA*2)
#define STB  (2*MATB)
template<int EPI>
__global__ __launch_bounds__(256, 2)
void gemm_tn_f16(const __half* __restrict__ A, int lda,
                 const __half* __restrict__ B, int ldb,
                 float* __restrict__ C, __half* __restrict__ Ch, int ldc,
                 const float* __restrict__ Sx, const float* __restrict__ rsx,
                 float* __restrict__ eup,
                 int M, int N, int K)
{
    __shared__ __half sm[2*2*128*SA];
    const unsigned sbase = (unsigned)__cvta_generic_to_shared(sm);
    const int bm = blockIdx.y * 128;
    const int bn = blockIdx.x * 128;
    const int tid  = threadIdx.x;
    const int warp = tid >> 5;
    const int lane = tid & 31;
    const int wm = (warp & 1) * 64;
    const int wn = (warp >> 1) * 32;
    const int g = lane >> 2;
    const int t = lane & 3;

    float acc[4][4][4];
    #pragma unroll
    for (int i = 0; i < 4; i++)
        #pragma unroll
        for (int j = 0; j < 4; j++)
            #pragma unroll
            for (int q = 0; q < 4; q++) acc[i][j][q] = 0.f;

    const int row  = tid >> 1;
    const int koff = (tid & 1) * 16;
    const __half* Ap = A + (size_t)(bm + row) * lda + koff;
    const __half* Bp = B + (size_t)(bn + row) * ldb + koff;
    const unsigned dA = sbase + (unsigned)((row*SA + koff) * 2);
    const unsigned dB = dA + MATB;
    const int szA = ((bm + row) < M) ? 16 : 0;

    const unsigned laneA = (unsigned)(((lane & 7) + ((lane >> 3) & 1) * 8) * SA
                                      + ((lane >> 4) & 1) * 8) * 2;
    const unsigned laneB = (unsigned)(((lane & 7) + ((lane >> 4) & 1) * 8) * SA
                                      + ((lane >> 3) & 1) * 8) * 2;

    const int nk = K >> 5;
    {
        cpasync16(dA,      Ap,     szA);
        cpasync16(dA + 16, Ap + 8, szA);
        cpasync16(dB,      Bp,     16);
        cpasync16(dB + 16, Bp + 8, 16);
        cp_commit();
    }

    for (int it = 0; it < nk; it++){
        const int st = it & 1;
        if (it + 1 < nk){
            const __half* ap = Ap + (it+1)*32;
            const __half* bp = Bp + (it+1)*32;
            const unsigned da = dA + (st^1)*STB;
            const unsigned db = dB + (st^1)*STB;
            cpasync16(da,      ap,     szA);
            cpasync16(da + 16, ap + 8, szA);
            cpasync16(db,      bp,     16);
            cpasync16(db + 16, bp + 8, 16);
        }
        cp_commit();
        cp_wait1();
        __syncthreads();

        const unsigned aBase = sbase + st*STB + laneA;
        const unsigned bBase = sbase + st*STB + MATB + laneB;
        #pragma unroll
        for (int ks = 0; ks < 2; ks++){
            unsigned aR[4][4];
            unsigned bR[4][2];
            #pragma unroll
            for (int mi = 0; mi < 4; mi++)
                ldm4(aR[mi][0], aR[mi][1], aR[mi][2], aR[mi][3],
                     aBase + (unsigned)(((wm + mi*16)*SA + ks*16) * 2));
            #pragma unroll
            for (int p = 0; p < 2; p++)
                ldm4(bR[2*p][0], bR[2*p][1], bR[2*p+1][0], bR[2*p+1][1],
                     bBase + (unsigned)(((wn + p*16)*SA + ks*16) * 2));
            #pragma unroll
            for (int mi = 0; mi < 4; mi++)
                #pragma unroll
                for (int ni = 0; ni < 4; ni++)
                    mma_f16(acc[mi][ni], aR[mi], bR[ni]);
        }
        __syncthreads();
    }

    if (EPI == 3){
        const bool isx = (bn < 256);
        const int h = bn >> 7;
        #pragma unroll
        for (int mi = 0; mi < 4; mi++){
            #pragma unroll
            for (int rr = 0; rr < 2; rr++){
                int r0 = bm + wm + mi*16 + g + rr*8;
                if (r0 >= M) continue;
                if (isx){
                    float rsv = rsx[h*NN + r0];
                    float rc = (rsv == 0.f) ? 1e-12f : rsv;
                    #pragma unroll
                    for (int ni = 0; ni < 4; ni++){
                        int c0 = bn + wn + ni*8 + 2*t;
                        float a0 = acc[mi][ni][rr*2], a1 = acc[mi][ni][rr*2+1];
                        float2 s = *reinterpret_cast<const float2*>(Sx + (size_t)r0*256 + c0);
                        *reinterpret_cast<__half2*>(Ch + (size_t)r0*256 + c0)
                            = __floats2half2_rn(elu1(fmaf(rsv, a0, s.x)/rc),
                                                elu1(fmaf(rsv, a1, s.y)/rc));
                    }
                } else {
                    #pragma unroll
                    for (int ni = 0; ni < 4; ni++){
                        int c0 = bn + wn + ni*8 + 2*t - 256;
                        *reinterpret_cast<float2*>(eup + (size_t)r0*256 + c0)
                            = make_float2(acc[mi][ni][rr*2], acc[mi][ni][rr*2+1]);
                    }
                }
            }
        }
        return;
    }

    #pragma unroll
    for (int mi = 0; mi < 4; mi++){
        #pragma unroll
        for (int rr = 0; rr < 2; rr++){
            int r0 = bm + wm + mi*16 + g + rr*8;
            if (r0 >= M) continue;
            #pragma unroll
            for (int ni = 0; ni < 4; ni++){
                int c0 = bn + wn + ni*8 + 2*t;
                float a0 = acc[mi][ni][rr*2], a1 = acc[mi][ni][rr*2+1];
                if (EPI == 0 || EPI == 1)
                    *reinterpret_cast<float2*>(C + (size_t)r0*ldc + c0) = make_float2(a0, a1);
                if (EPI == 1 || EPI == 2)
                    *reinterpret_cast<__half2*>(Ch + (size_t)r0*ldc + c0) = __floats2half2_rn(a0, a1);
            }
        }
    }
}

// ---------------- edge gather helper (fp16) ----------------
__device__ __forceinline__ float4 ldh4f(const __half* p){
    const __half2* q = reinterpret_cast<const __half2*>(p);
    float2 a = __half22float2(q[0]), b = __half22float2(q[1]);
    return make_float4(a.x, a.y, b.x, b.y);
}

// ---------------- layer-1 edge kernel: both heads fused, warp/edge ----------------
__global__ void k_edge1(const int* __restrict__ el, const int* __restrict__ eln,
                        const int* __restrict__ et, const int* __restrict__ etn,
                        const float* __restrict__ sd, const float* __restrict__ ss,
                        const float* __restrict__ sr,
                        const __half* __restrict__ Ps, const __half* __restrict__ R,
                        float* __restrict__ rs, float* __restrict__ S)
{
    int e = (blockIdx.x * blockDim.x + threadIdx.x) >> 5;
    int lane = threadIdx.x & 31;
    if (e >= ET) return;
    int dst, src, r0, r1 = -1;
    bool onehop = (e < E1);
    if (onehop){
        dst = el[e]; src = el[E1 + e]; r0 = et[e];
    } else {
        int i = e - E1;
        dst = eln[i]; src = eln[EN + i];
        r0 = etn[2*i]; r1 = etn[2*i + 1];
    }
    float ee0, ee1;
    if (lane == 0){
        float sr0 = onehop ? sr[r0]       : (sr[r0]       + sr[r1]);
        float sr1v= onehop ? sr[NREL+r0]  : (sr[NREL+r0]  + sr[NREL+r1]);
        float s0 = sd[dst]      + ss[src]      + sr0;
        float s1 = sd[NN + dst] + ss[NN + src] + sr1v;
        float lk0 = s0 > 0.f ? s0 : 0.2f * s0;
        float lk1 = s1 > 0.f ? s1 : 0.2f * s1;
        ee0 = expf(-lk0);
        ee1 = expf(-lk1);
        atomicAdd(rs + dst, ee0);
        atomicAdd(rs + NN + dst, ee1);
    }
    ee0 = __shfl_sync(0xffffffffu, ee0, 0);
    ee1 = __shfl_sync(0xffffffffu, ee1, 0);
    #pragma unroll
    for (int c0 = 0; c0 < 256; c0 += 128){
        int c = c0 + lane * 4;
        float ee = c0 ? ee1 : ee0;
        float4 p = ldh4f(Ps + (size_t)src * 256 + c);
        float4 r = ldh4f(R + (size_t)r0 * 256 + c);
        if (!onehop){
            float4 rb = ldh4f(R + (size_t)r1 * 256 + c);
            r.x += rb.x; r.y += rb.y; r.z += rb.z; r.w += rb.w;
        }
        red4(S + (size_t)dst * 256 + c,
             make_float4(ee*(p.x+r.x), ee*(p.y+r.y), ee*(p.z+r.z), ee*(p.w+r.w)));
    }
}

// ---------------- layer-2 edge kernel, warp/edge ----------------
__global__ void k_edge2(const int* __restrict__ el, const int* __restrict__ eln,
                        const int* __restrict__ et, const int* __restrict__ etn,
                        const float* __restrict__ sd, const float* __restrict__ ss,
                        const float* __restrict__ sr,
                        const __half* __restrict__ Xs, const __half* __restrict__ R,
                        float* __restrict__ rs, float* __restrict__ S)
{
    int e = (blockIdx.x * blockDim.x + threadIdx.x) >> 5;
    int lane = threadIdx.x & 31;
    if (e >= ET) return;
    int dst, src, r0, r1 = -1;
    bool onehop = (e < E1);
    if (onehop){
        dst = el[e]; src = el[E1 + e]; r0 = et[e];
    } else {
        int i = e - E1;
        dst = eln[i]; src = eln[EN + i];
        r0 = etn[2*i]; r1 = etn[2*i + 1];
    }
    float ee;
    if (lane == 0){
        float srv = onehop ? sr[r0] : (sr[r0] + sr[r1]);
        float s = sd[dst] + ss[src] + srv;
        float lk = s > 0.f ? s : 0.2f * s;
        ee = expf(-lk);
        atomicAdd(rs + dst, ee);
    }
    ee = __shfl_sync(0xffffffffu, ee, 0);
    #pragma unroll
    for (int c0 = 0; c0 < 256; c0 += 128){
        int c = c0 + lane * 4;
        float4 p = ldh4f(Xs + (size_t)src * 256 + c);
        float4 r = ldh4f(R + (size_t)r0 * 256 + c);
        if (!onehop){
            float4 rb = ldh4f(R + (size_t)r1 * 256 + c);
            r.x += rb.x; r.y += rb.y; r.z += rb.z; r.w += rb.w;
        }
        red4(S + (size_t)dst * 256 + c,
             make_float4(ee*(p.x+r.x), ee*(p.y+r.y), ee*(p.z+r.z), ee*(p.w+r.w)));
    }
}

// ---------------- final outputs ----------------
__global__ void k_final(const float* __restrict__ eup, const float* __restrict__ Xd,
                        const float* __restrict__ S2, const float* __restrict__ rs2,
                        const float* __restrict__ mask,
                        float* __restrict__ out1, float* __restrict__ out3)
{
    int n = (blockIdx.x * blockDim.x + threadIdx.x) >> 5;
    int lane = threadIdx.x & 31;
    if (n >= NN) return;
    float r  = rs2[n];
    float rc = (r == 0.f) ? 1e-12f : r;
    float mk = mask[n];
    float4 v1[2], v3[2];
    float ss1 = 0.f, ss3 = 0.f;
    #pragma unroll
    for (int q = 0; q < 2; q++){
        int c = q*128 + lane*4;
        float4 xd = ld4(Xd + (size_t)n*256 + c);
        float4 s2 = ld4(S2 + (size_t)n*256 + c);
        float4 e4 = ld4(eup + (size_t)n*256 + c);
        float hr0 = fmaf(r, xd.x, s2.x);
        float hr1 = fmaf(r, xd.y, s2.y);
        float hr2 = fmaf(r, xd.z, s2.z);
        float hr3 = fmaf(r, xd.w, s2.w);
        float a0 = e4.x + mk * elu1(hr0 / rc);
        float a1 = e4.y + mk * elu1(hr1 / rc);
        float a2 = e4.z + mk * elu1(hr2 / rc);
        float a3 = e4.w + mk * elu1(hr3 / rc);
        float b0 = elu1(hr0), b1 = elu1(hr1), b2 = elu1(hr2), b3 = elu1(hr3);
        v1[q] = make_float4(a0, a1, a2, a3);
        v3[q] = make_float4(b0, b1, b2, b3);
        ss1 += a0*a0 + a1*a1 + a2*a2 + a3*a3;
        ss3 += b0*b0 + b1*b1 + b2*b2 + b3*b3;
    }
    ss1 = wred(ss1);
    ss3 = wred(ss3);
    float sc1 = 1.f / fmaxf(sqrtf(ss1), 1e-12f);
    float sc3 = 1.f / fmaxf(sqrtf(ss3), 1e-12f);
    #pragma unroll
    for (int q = 0; q < 2; q++){
        int c = q*128 + lane*4;
        st4(out1 + (size_t)n*256 + c, make_float4(v1[q].x*sc1, v1[q].y*sc1, v1[q].z*sc1, v1[q].w*sc1));
        st4(out3 + (size_t)n*256 + c, make_float4(v3[q].x*sc3, v3[q].y*sc3, v3[q].z*sc3, v3[q].w*sc3));
    }
}

// ---------------- host launch ----------------
static void* symv(const void* s){
    void* p = nullptr;
    cudaGetSymbolAddress(&p, s);
    return p;
}

extern "C" void kernel_launch(void* const* d_in, const int* in_sizes, int n_in,
                              void* d_out, int out_size)
{
    const float* ent    = (const float*)d_in[0];
    const float* rel    = (const float*)d_in[1];
    const float* a1     = (const float*)d_in[2];
    const float* a2_1   = (const float*)d_in[3];
    const float* W      = (const float*)d_in[4];
    const float* a_out  = (const float*)d_in[5];
    const float* a2_out = (const float*)d_in[6];
    const float* W_ent  = (const float*)d_in[7];
    const int*   bi     = (const int*)d_in[8];
    const int*   el     = (const int*)d_in[9];
    const int*   et     = (const int*)d_in[10];
    const int*   eln    = (const int*)d_in[11];
    const int*   etn    = (const int*)d_in[12];
    float* out = (float*)d_out;

    float* Z      = (float*)symv(g_Z);
    float* p_S1   = Z + OFF_S1;
    float* p_S2   = Z + OFF_S2;
    float* p_rs1  = Z + OFF_RS1;
    float* p_rs2  = Z + OFF_RS2;
    float* p_mask = Z + OFF_MASK;
    __half* entH  = (__half*)symv(g_entH);
    __half* xH    = (__half*)symv(g_xH);
    __half* orelH = (__half*)symv(g_orelH);
    __half* PsH   = (__half*)symv(g_PsH);
    __half* XsH   = (__half*)symv(g_XsH);
    __half* R1H   = (__half*)symv(g_R1H);
    __half* R2H   = (__half*)symv(g_R2H);
    float* p_eup  = (float*)symv(g_eup);
    float* p_Xd   = (float*)symv(g_Xd);
    float* p_sd1  = (float*)symv(g_sd1); float* p_ss1 = (float*)symv(g_ss1);
    float* p_sr1  = (float*)symv(g_sr1); float* p_sd2 = (float*)symv(g_sd2);
    float* p_ss2  = (float*)symv(g_ss2); float* p_sr2 = (float*)symv(g_sr2);
    float* p_wv   = (float*)symv(g_wv);
    __half* B1d = (__half*)symv(hB1d); __half* B1s = (__half*)symv(hB1s);
    __half* BR1 = (__half*)symv(hBR1); __half* B2d = (__half*)symv(hB2d);
    __half* B2s = (__half*)symv(hB2s); __half* B3  = (__half*)symv(hB3);
    __half* BW  = (__half*)symv(hBW);  __half* relH= (__half*)symv(g_relH);

    const int T = 256;
    const int GY = (NN + 127) / 128;
    const int GW = (NN*32 + T - 1) / T;
    const int GE = (ET*32 + T - 1) / T;
    const int NPACK = 512*128 + 2*256*128 + 3*256*256 + 2*256*128;

    // 1: zero scratch
    k_zero4<<<4096, T>>>((float4*)Z, ZN/4);
    // 2: pack fp16 weights + relH
    k_packs<<<(NPACK + T-1)/T, T>>>(a1, a_out, W, W_ent, rel,
                                    B1d, B1s, BR1, B2d, B2s, B3, BW, relH);
    // 3: l2 normalize entities -> fp16
    k_l2norm128<<<GW, T>>>(ent, entH);
    // 4: Ps GEMM -> fp16 only (profiled launch)
    gemm_tn_f16<2><<<dim3(2, GY), T>>>(entH, 128, B1s, 128, nullptr, PsH, 256,
                                       nullptr, nullptr, nullptr, NN, 256, 128);
    // 5: R1 GEMM -> fp16 only
    gemm_tn_f16<2><<<dim3(2, 2), T>>>(relH, 128, BR1, 128, nullptr, R1H, 256,
                                      nullptr, nullptr, nullptr, NREL, 256, 128);
    // 6: w vectors
    k_wvec<<<9, 256>>>(B1d, B1s, BR1, B2d, B2s, B3, a2_1, a2_out, p_wv);
    // 7: layer-1 node scalars
    k_scal1<<<GW, T>>>(entH, p_wv, p_sd1, p_ss1);
    // 8: layer-1 relation scalars
    k_scalrel1<<<(NREL*32 + T-1)/T, T>>>(relH, p_wv, p_sr1);
    // 9: fused 2-head edge scatter
    k_edge1<<<GE, T>>>(el, eln, et, etn, p_sd1, p_ss1, p_sr1, PsH, R1H, p_rs1, p_S1);
    // 10: Pd GEMM with fused fin1 epilogue -> xH + eup
    gemm_tn_f16<3><<<dim3(4, GY), T>>>(entH, 128, B1d, 128, nullptr, xH, 0,
                                       p_S1, p_rs1, p_eup, NN, 512, 128);
    // 11: out_relation_1 = rel @ W (fp32 out + fp16 copy)
    gemm_tn_f16<1><<<dim3(2, 2), T>>>(relH, 128, BW, 128, out + OREL, orelH, 256,
                                      nullptr, nullptr, nullptr, NREL, 256, 128);
    // 12: Xs GEMM -> fp16 only
    gemm_tn_f16<2><<<dim3(2, GY), T>>>(xH, 256, B2s, 256, nullptr, XsH, 256,
                                       nullptr, nullptr, nullptr, NN, 256, 256);
    // 13: R2 GEMM -> fp16 only
    gemm_tn_f16<2><<<dim3(2, 2), T>>>(orelH, 256, B3, 256, nullptr, R2H, 256,
                                      nullptr, nullptr, nullptr, NREL, 256, 256);
    // 14: layer-2 node scalars
    k_scal2<<<GW, T>>>(xH, p_wv, p_sd2, p_ss2);
    // 15: layer-2 relation scalars
    k_scalrel2<<<(NREL*32 + T-1)/T, T>>>(orelH, p_wv, p_sr2);
    // 16: layer-2 edge scatter
    k_edge2<<<GE, T>>>(el, eln, et, etn, p_sd2, p_ss2, p_sr2, XsH, R2H, p_rs2, p_S2);
    // 17: Xd GEMM -> fp32
    gemm_tn_f16<0><<<dim3(2, GY), T>>>(xH, 256, B2d, 256, p_Xd, nullptr, 256,
                                       nullptr, nullptr, nullptr, NN, 256, 256);
    // 18: mask scatter
    k_setmask<<<16, T>>>(bi, p_mask);
    // 19: final outputs
    k_final<<<GW, T>>>(p_eup, p_Xd, p_S2, p_rs2, p_mask, out, out + O3);
}